// round 2
// baseline (speedup 1.0000x reference)
#include <cuda_runtime.h>

// out[t,b,i,e] = x[t,b,i] * W[i,e] + b[e]
// T=8, B=64, D=512, E=256
// rows = T*B*D = 262144 ; each row emits E=256 floats = 64 float4s.
// Thread v: e4 = v & 63, row = v >> 6, i = row & 511.

#define D_DIM 512
#define E_DIM 256
#define E4    (E_DIM / 4)          // 64 float4 per row
#define ROWS  (8 * 64 * 512)       // 262144
#define TOTAL4 (ROWS * E4)         // 16,777,216 float4 stores

__global__ __launch_bounds__(256) void dense_embed_kernel(
    const float* __restrict__ x,   // [ROWS]
    const float4* __restrict__ W4, // [D_DIM * E4]
    const float4* __restrict__ b4, // [E4]
    float4* __restrict__ out4)     // [TOTAL4]
{
    unsigned v = blockIdx.x * 256u + threadIdx.x;   // grid sized exactly
    unsigned e4  = v & (E4 - 1);
    unsigned row = v >> 6;
    unsigned i   = row & (D_DIM - 1);

    float   xv = __ldg(&x[row]);            // broadcast across 64-thread group
    float4  w  = __ldg(&W4[i * E4 + e4]);   // coalesced, L2-resident
    float4  bb = __ldg(&b4[e4]);            // L1-resident

    float4 o;
    o.x = fmaf(xv, w.x, bb.x);
    o.y = fmaf(xv, w.y, bb.y);
    o.z = fmaf(xv, w.z, bb.z);
    o.w = fmaf(xv, w.w, bb.w);
    out4[v] = o;
}

extern "C" void kernel_launch(void* const* d_in, const int* in_sizes, int n_in,
                              void* d_out, int out_size) {
    const float*  x  = (const float*)d_in[0];
    const float4* W4 = (const float4*)d_in[1];
    const float4* b4 = (const float4*)d_in[2];
    float4* out4 = (float4*)d_out;

    dim3 grid(TOTAL4 / 256);  // 65536 blocks
    dense_embed_kernel<<<grid, 256>>>(x, W4, b4, out4);
}

// round 4
// speedup vs baseline: 1.4086x; 1.4086x over previous
#include <cuda_runtime.h>

// out[t,b,i,e] = x[t,b,i] * W[i,e] + b[e]
// T=8, B=64, D=512, E=256. Let k = t*B+b in [0,512).
// out4[(k*512 + i)*64 + e4] = x[k*512 + i] * W4[i*64 + e4] + b4[e4]
//
// Grid: x = i (512), y = k-chunk (8 chunks of 64 k's).
// Block: 256 threads = 4 k-lanes (kg) x 64 e4-lanes.
// Each thread: W/b in registers, loop 16 k values -> 16 STG.128.

#define D_DIM 512
#define E4    64
#define K_TOT 512          // T*B
#define K_CHUNKS 8
#define K_PER_CHUNK 64     // 4 kg-lanes * 16 iters

__global__ __launch_bounds__(256) void dense_embed_kernel(
    const float* __restrict__ x,    // [K_TOT * D_DIM]
    const float4* __restrict__ W4,  // [D_DIM * E4]
    const float4* __restrict__ b4,  // [E4]
    float4* __restrict__ out4)      // [K_TOT * D_DIM * E4]
{
    const unsigned i  = blockIdx.x;               // 0..511
    const unsigned e4 = threadIdx.x & (E4 - 1);   // 0..63
    const unsigned kg = threadIdx.x >> 6;         // 0..3
    const unsigned k0 = blockIdx.y * K_PER_CHUNK + kg * 16;

    // Per-thread invariants, loaded once
    const float4 w  = __ldg(&W4[i * E4 + e4]);
    const float4 bb = __ldg(&b4[e4]);

    const float* xp = x + i;                         // x[k*512 + i]
    float4* op = out4 + ((size_t)k0 * D_DIM + i) * E4 + e4;

    #pragma unroll 4
    for (int kk = 0; kk < 16; kk++) {
        const unsigned k = k0 + kk;
        const float xv = __ldg(&xp[(size_t)k * D_DIM]);  // uniform per warp
        float4 o;
        o.x = fmaf(xv, w.x, bb.x);
        o.y = fmaf(xv, w.y, bb.y);
        o.z = fmaf(xv, w.z, bb.z);
        o.w = fmaf(xv, w.w, bb.w);
        __stcs(&op[(size_t)kk * D_DIM * E4], o);     // evict-first streaming store
    }
}

extern "C" void kernel_launch(void* const* d_in, const int* in_sizes, int n_in,
                              void* d_out, int out_size) {
    const float*  x  = (const float*)d_in[0];
    const float4* W4 = (const float4*)d_in[1];
    const float4* b4 = (const float4*)d_in[2];
    float4* out4 = (float4*)d_out;

    dim3 grid(D_DIM, K_CHUNKS);   // 512 x 8 = 4096 blocks
    dense_embed_kernel<<<grid, 256>>>(x, W4, b4, out4);
}

// round 6
// speedup vs baseline: 1.4119x; 1.0023x over previous
#include <cuda_runtime.h>

// out[t,b,i,e] = x[t,b,i] * W[i,e] + b[e]
// T=8, B=64, D=512, E=256. k = t*B+b in [0,512).
// out4[(k*512 + i)*64 + e4] = x[k*512 + i] * W4[i*64 + e4] + b4[e4]
//
// Grid: x = i (512), y = k-chunk (8). Block: 256 thr = 4 kg x 64 e4.
// Each thread: W/b in regs; batch-load 16 x values (MLP=16), then 16 FMA4+STG.128.

#define D_DIM 512
#define E4    64
#define K_CHUNKS 8
#define K_PER_CHUNK 64
#define KK 16

__global__ __launch_bounds__(256) void dense_embed_kernel(
    const float* __restrict__ x,    // [512 * 512]
    const float4* __restrict__ W4,  // [512 * 64]
    const float4* __restrict__ b4,  // [64]
    float4* __restrict__ out4)      // [512 * 512 * 64]
{
    const unsigned i  = blockIdx.x;               // 0..511
    const unsigned e4 = threadIdx.x & (E4 - 1);   // 0..63
    const unsigned kg = threadIdx.x >> 6;         // 0..3
    const unsigned k0 = blockIdx.y * K_PER_CHUNK + kg * KK;

    // Per-thread invariants
    const float4 w  = __ldg(&W4[i * E4 + e4]);
    const float4 bb = __ldg(&b4[e4]);

    const float* xp = x + (size_t)k0 * D_DIM + i;
    float4* op = out4 + ((size_t)k0 * D_DIM + i) * E4 + e4;

    // Batch all 16 x loads up front — 16 outstanding uniform LDGs.
    float xv[KK];
    #pragma unroll
    for (int kk = 0; kk < KK; kk++)
        xv[kk] = __ldg(&xp[(size_t)kk * D_DIM]);

    // Then a pure store stream: 16 back-to-back FMA4 + STG.128.
    #pragma unroll
    for (int kk = 0; kk < KK; kk++) {
        float4 o;
        o.x = fmaf(xv[kk], w.x, bb.x);
        o.y = fmaf(xv[kk], w.y, bb.y);
        o.z = fmaf(xv[kk], w.z, bb.z);
        o.w = fmaf(xv[kk], w.w, bb.w);
        __stcs(&op[(size_t)kk * D_DIM * E4], o);
    }
}

extern "C" void kernel_launch(void* const* d_in, const int* in_sizes, int n_in,
                              void* d_out, int out_size) {
    const float*  x  = (const float*)d_in[0];
    const float4* W4 = (const float4*)d_in[1];
    const float4* b4 = (const float4*)d_in[2];
    float4* out4 = (float4*)d_out;

    dim3 grid(D_DIM, K_CHUNKS);   // 4096 blocks
    dense_embed_kernel<<<grid, 256>>>(x, W4, b4, out4);
}